// round 8
// baseline (speedup 1.0000x reference)
#include <cuda_runtime.h>
#include <cstdint>

#define NU 100000
#define NI 50000
#define NN 150000

typedef unsigned long long ull;

// ---------------------------------------------------------------------------
// f32x2 packed-FMA helpers (Blackwell): FFMA2 in SASS
// ---------------------------------------------------------------------------
__device__ __forceinline__ ull pack2(float x, float y) {
    ull r; asm("mov.b64 %0, {%1, %2};" : "=l"(r) : "f"(x), "f"(y)); return r;
}
__device__ __forceinline__ float2 unpack2(ull v) {
    float2 r; asm("mov.b64 {%0, %1}, %2;" : "=f"(r.x), "=f"(r.y) : "l"(v)); return r;
}
__device__ __forceinline__ void fma2(ull& d, ull a, ull b) {
    asm("fma.rn.f32x2 %0, %1, %2, %0;" : "+l"(d) : "l"(a), "l"(b));
}

// ---------------------------------------------------------------------------
// Device-global scratch
// ---------------------------------------------------------------------------
__device__ float g_PT[64 * 32];     // PT[k][i] : transposed score projection (scaled 1/4)
__device__ float g_C[8 * 32];       // C[t0][i]
__device__ float g_WvWo[64 * 64];   // Wv @ Wo
__device__ float g_VoffO[32 * 64];  // VoffO[i][j]
__device__ int   g_ei64;
__device__ int   g_ti64;

__device__ float g_X[(size_t)NN * 64];
__device__ float g_H0[(size_t)NN * 64];
__device__ float g_H1[(size_t)NN * 64];
__device__ float g_AGG[(size_t)NN * 64];

// ---------------------------------------------------------------------------
// Kernel 1: precompute, 4 blocks (proven in R5)
// ---------------------------------------------------------------------------
__global__ void __launch_bounds__(256) precompute_kernel(
    const float* __restrict__ te,
    const float* __restrict__ Wq, const float* __restrict__ bq,
    const float* __restrict__ Wk, const float* __restrict__ bk,
    const float* __restrict__ Wv, const float* __restrict__ bv,
    const float* __restrict__ Wo,
    const void* __restrict__ ei_raw, const void* __restrict__ ti_raw)
{
    __shared__ float qoff[512], koff[512], voff[512];
    __shared__ float sWo[4096];
    int t = threadIdx.x;
    int blk = blockIdx.x;

    for (int idx = t; idx < 512; idx += 256) {
        int tt = idx >> 6, d = idx & 63;
        float q = bq[d], k = bk[d], v = bv[d];
        for (int j = 0; j < 64; j++) {
            float x = __ldg(te + tt * 64 + j);
            q += x * __ldg(Wq + j * 64 + d);
            k += x * __ldg(Wk + j * 64 + d);
            v += x * __ldg(Wv + j * 64 + d);
        }
        qoff[idx] = q; koff[idx] = k; voff[idx] = v;
    }
    if (blk >= 1) {
        for (int i = t; i < 4096; i += 256) sWo[i] = __ldg(Wo + i);
    }
    __syncthreads();

    if (blk == 0) {
        for (int idx = t; idx < 2048; idx += 256) {
            int j = idx >> 5, i = idx & 31;
            int h = i >> 3, tt = i & 7;
            float s = 0.f;
            #pragma unroll
            for (int m = 0; m < 16; m++)
                s += __ldg(Wq + j * 64 + h * 16 + m) * koff[tt * 64 + h * 16 + m];
            g_PT[idx] = 0.25f * s;
        }
        for (int idx = t; idx < 256; idx += 256) {
            int t0 = idx >> 5, i = idx & 31;
            int h = i >> 3, tt = i & 7;
            float s = 0.f;
            #pragma unroll
            for (int m = 0; m < 16; m++)
                s += qoff[t0 * 64 + h * 16 + m] * koff[tt * 64 + h * 16 + m];
            g_C[idx] = 0.25f * s;
        }
        if (t == 0) {
            const int* e32 = (const int*)ei_raw;
            const int* t32 = (const int*)ti_raw;
            int is64 = 1;
            for (int i = 0; i < 64; i++) if (e32[2 * i + 1] != 0) { is64 = 0; break; }
            g_ei64 = is64;
            is64 = 1;
            for (int i = 0; i < 64; i++) if (t32[2 * i + 1] != 0) { is64 = 0; break; }
            g_ti64 = is64;
        }
    } else if (blk == 1) {
        for (int idx = t; idx < 2048; idx += 256) {
            int i = idx >> 6, j = idx & 63;
            int h = i >> 3, tt = i & 7;
            float s = 0.f;
            #pragma unroll
            for (int m = 0; m < 16; m++)
                s += voff[tt * 64 + h * 16 + m] * sWo[(h * 16 + m) * 64 + j];
            g_VoffO[idx] = s;
        }
    } else {
        int kbase = (blk - 2) * 32;
        int k = kbase + (t >> 3);
        int j0 = (t & 7) * 8;
        float xv[64];
        #pragma unroll 16
        for (int d = 0; d < 64; d++) xv[d] = __ldg(Wv + k * 64 + d);
        float acc[8];
        #pragma unroll
        for (int j = 0; j < 8; j++) acc[j] = 0.f;
        for (int d = 0; d < 64; d++) {
            float x = xv[d];
            #pragma unroll
            for (int j = 0; j < 8; j++) acc[j] += x * sWo[d * 64 + j0 + j];
        }
        #pragma unroll
        for (int j = 0; j < 8; j++) g_WvWo[k * 64 + j0 + j] = acc[j];
    }
}

// ---------------------------------------------------------------------------
// Kernel 2: node kernel — warp-autonomous, 4 nodes per warp per iteration.
// Weights staged once per block; inner loops use pre-duplicated x in smem
// (one LDS.64 = packed broadcast operand) and packed weight pairs.
// ---------------------------------------------------------------------------
__global__ void __launch_bounds__(256) node_kernel(
    const float* __restrict__ user_emb,
    const float* __restrict__ item_emb,
    const void* __restrict__ ti_raw,
    const float* __restrict__ te,
    const float* __restrict__ bo,
    const float* __restrict__ causal,
    int numGroups)
{
    __shared__ ull   sWv2[64][32];   // 16KB : pack(WvWo[k][2l], WvWo[k][2l+1])
    __shared__ ull   sVO2[32][32];   // 8KB  : pack(VoffO[i][2l], VoffO[i][2l+1])
    __shared__ ull   sXd[8][4][64];  // 16KB : per-warp x duplicated (x[j],x[j])
    __shared__ float sTE[512];       // 2KB
    __shared__ float sC[256];        // 1KB

    int t = threadIdx.x;
    int w = t >> 5, lane = t & 31;
    int ti64 = g_ti64;

    for (int i = t; i < 2048; i += 256) {
        int k = i >> 5, l = i & 31;
        float2 v = *(const float2*)(g_WvWo + k * 64 + 2 * l);
        sWv2[k][l] = pack2(v.x, v.y);
    }
    for (int i = t; i < 1024; i += 256) {
        int r = i >> 5, l = i & 31;
        float2 v = *(const float2*)(g_VoffO + r * 64 + 2 * l);
        sVO2[r][l] = pack2(v.x, v.y);
    }
    for (int i = t; i < 512; i += 256) sTE[i] = __ldg(te + i);
    sC[t] = g_C[t];
    __syncthreads();

    float2 bo2 = __ldg((const float2*)bo + lane);
    ull bias_u = pack2(bo2.x, bo2.y);
    const unsigned FULL = 0xffffffffu;

    int gwarp = blockIdx.x * 8 + w;
    int nWarps = gridDim.x * 8;

    for (int gi = gwarp; gi < numGroups; gi += nWarps) {
        int base = gi * 4;

        // stage x (duplicated) for 4 nodes
        #pragma unroll
        for (int m = 0; m < 4; m++) {
            int n = base + m;
            float2 x2 = make_float2(0.f, 0.f);
            if (n < NN) {
                const float* src = (n < NU) ? user_emb + (size_t)n * 64
                                            : item_emb + (size_t)(n - NU) * 64;
                x2 = __ldg((const float2*)src + lane);
            }
            ulonglong2 pv;
            pv.x = pack2(x2.x, x2.x);
            pv.y = pack2(x2.y, x2.y);
            *(ulonglong2*)&sXd[w][m][2 * lane] = pv;
        }
        int tv = 0;
        if (lane < 4) {
            int n = base + lane;
            if (n < NN)
                tv = ti64 ? (int)__ldg((const long long*)ti_raw + n)
                          : __ldg((const int*)ti_raw + n);
        }
        __syncwarp();

        int t00 = __shfl_sync(FULL, tv, 0);
        int t01 = __shfl_sync(FULL, tv, 1);
        int t02 = __shfl_sync(FULL, tv, 2);
        int t03 = __shfl_sync(FULL, tv, 3);

        // scores: lane = combo i
        const float* xf0 = (const float*)sXd[w][0];
        const float* xf1 = (const float*)sXd[w][1];
        const float* xf2 = (const float*)sXd[w][2];
        const float* xf3 = (const float*)sXd[w][3];
        float s0 = 0.f, s1 = 0.f, s2 = 0.f, s3 = 0.f;
        #pragma unroll 8
        for (int k = 0; k < 64; k++) {
            float p = __ldg(g_PT + k * 32 + lane);
            s0 += p * xf0[2 * k];
            s1 += p * xf1[2 * k];
            s2 += p * xf2[2 * k];
            s3 += p * xf3[2 * k];
        }
        s0 += sC[t00 * 32 + lane];
        s1 += sC[t01 * 32 + lane];
        s2 += sC[t02 * 32 + lane];
        s3 += sC[t03 * 32 + lane];

        // softmax over 8 timesteps (lanes i = h*8+t; xor within 8-lane groups)
        float a0, a1, a2, a3;
        {
            float m0 = fmaxf(s0, __shfl_xor_sync(FULL, s0, 1));
            m0 = fmaxf(m0, __shfl_xor_sync(FULL, m0, 2));
            m0 = fmaxf(m0, __shfl_xor_sync(FULL, m0, 4));
            float e = __expf(s0 - m0);
            float u = e + __shfl_xor_sync(FULL, e, 1);
            u += __shfl_xor_sync(FULL, u, 2);
            u += __shfl_xor_sync(FULL, u, 4);
            a0 = e / u;
        }
        {
            float m0 = fmaxf(s1, __shfl_xor_sync(FULL, s1, 1));
            m0 = fmaxf(m0, __shfl_xor_sync(FULL, m0, 2));
            m0 = fmaxf(m0, __shfl_xor_sync(FULL, m0, 4));
            float e = __expf(s1 - m0);
            float u = e + __shfl_xor_sync(FULL, e, 1);
            u += __shfl_xor_sync(FULL, u, 2);
            u += __shfl_xor_sync(FULL, u, 4);
            a1 = e / u;
        }
        {
            float m0 = fmaxf(s2, __shfl_xor_sync(FULL, s2, 1));
            m0 = fmaxf(m0, __shfl_xor_sync(FULL, m0, 2));
            m0 = fmaxf(m0, __shfl_xor_sync(FULL, m0, 4));
            float e = __expf(s2 - m0);
            float u = e + __shfl_xor_sync(FULL, e, 1);
            u += __shfl_xor_sync(FULL, u, 2);
            u += __shfl_xor_sync(FULL, u, 4);
            a2 = e / u;
        }
        {
            float m0 = fmaxf(s3, __shfl_xor_sync(FULL, s3, 1));
            m0 = fmaxf(m0, __shfl_xor_sync(FULL, m0, 2));
            m0 = fmaxf(m0, __shfl_xor_sync(FULL, m0, 4));
            float e = __expf(s3 - m0);
            float u = e + __shfl_xor_sync(FULL, e, 1);
            u += __shfl_xor_sync(FULL, u, 2);
            u += __shfl_xor_sync(FULL, u, 4);
            a3 = e / u;
        }

        // out accumulators (packed cols 2l,2l+1), bias pre-added
        ull acc0 = bias_u, acc1 = bias_u, acc2 = bias_u, acc3 = bias_u;

        // x @ WvWo
        #pragma unroll 8
        for (int k = 0; k < 64; k++) {
            ull wv = sWv2[k][lane];
            fma2(acc0, sXd[w][0][k], wv);
            fma2(acc1, sXd[w][1][k], wv);
            fma2(acc2, sXd[w][2][k], wv);
            fma2(acc3, sXd[w][3][k], wv);
        }
        // attn @ VoffO
        #pragma unroll 8
        for (int i = 0; i < 32; i++) {
            ull vo = sVO2[i][lane];
            float b0 = __shfl_sync(FULL, a0, i);
            float b1 = __shfl_sync(FULL, a1, i);
            float b2 = __shfl_sync(FULL, a2, i);
            float b3 = __shfl_sync(FULL, a3, i);
            fma2(acc0, pack2(b0, b0), vo);
            fma2(acc1, pack2(b1, b1), vo);
            fma2(acc2, pack2(b2, b2), vo);
            fma2(acc3, pack2(b3, b3), vo);
        }

        // epilogue
        #pragma unroll
        for (int m = 0; m < 4; m++) {
            int n = base + m;
            if (n >= NN) continue;
            ull a = (m == 0) ? acc0 : (m == 1) ? acc1 : (m == 2) ? acc2 : acc3;
            int t0 = (m == 0) ? t00 : (m == 1) ? t01 : (m == 2) ? t02 : t03;
            const float* xf = (const float*)sXd[w][m];
            float2 r = unpack2(a);
            r.x += xf[4 * lane]     + sTE[t0 * 64 + 2 * lane];
            r.y += xf[4 * lane + 2] + sTE[t0 * 64 + 2 * lane + 1];
            *((float2*)(g_X + (size_t)n * 64) + lane) = r;
            float2 cz = __ldg((const float2*)(causal + (size_t)n * 64) + lane);
            float2 h = make_float2(r.x + 0.5f * cz.x, r.y + 0.5f * cz.y);
            *((float2*)(g_H0 + (size_t)n * 64) + lane) = h;
            *((float2*)(g_AGG + (size_t)n * 64) + lane) = make_float2(0.f, 0.f);
        }
        __syncwarp();
    }
}

// ---------------------------------------------------------------------------
// Kernel 3: edge scatter — at REDG lane floor, unchanged.
// ---------------------------------------------------------------------------
__global__ void __launch_bounds__(256) scatter_kernel(
    const void* __restrict__ ei_raw, int E, int mode)
{
    const float* __restrict__ H = mode ? g_H1 : g_H0;
    int gw = (int)((blockIdx.x * (unsigned)blockDim.x + threadIdx.x) >> 5);
    int lane = threadIdx.x & 31;
    int half = lane >> 4, sub = lane & 15;
    long long e = (long long)gw * 2 + half;
    bool valid = (e < (long long)E);
    long long ec = valid ? e : 0;

    long long src, dst;
    if (g_ei64) {
        const long long* p = (const long long*)ei_raw;
        src = p[ec];
        dst = p[(size_t)E + ec];
    } else {
        const int* p = (const int*)ei_raw;
        src = p[ec];
        dst = p[(size_t)E + ec];
    }
    if (valid) {
        float4 v = *((const float4*)(H + (size_t)src * 64) + sub);
        float* dp = g_AGG + (size_t)dst * 64 + sub * 4;
        asm volatile("red.global.add.v4.f32 [%0], {%1,%2,%3,%4};"
                     :: "l"(dp), "f"(v.x), "f"(v.y), "f"(v.z), "f"(v.w)
                     : "memory");
    }
}

// ---------------------------------------------------------------------------
// Kernel 4: dense layer — warp-autonomous, 2 nodes per warp per iteration.
// Interleaved packed weights: one LDS.128 per k yields (Ws-pair, Wn-pair).
// Inputs pre-duplicated in smem: one LDS.64 per node per matrix per k.
// Inner loop/k: 1 LDS.128 + 4 LDS.64 + 8 FFMA2 = 32 MACs.
// mode 0: relu(h0@Ws + agg@Wn + b) -> g_H1, re-zero AGG.
// mode 1: out = g_X + relu(h1@Ws + agg@Wn + b) (+ dup copy).
// ---------------------------------------------------------------------------
__global__ void __launch_bounds__(256) dense_kernel(
    const float* __restrict__ Ws, const float* __restrict__ Wn,
    const float* __restrict__ bb,
    float* __restrict__ out, int dup, int numGroups, int mode)
{
    __shared__ ulonglong2 sW4[64][32];    // 32KB : {pack(Ws[k][2l..]), pack(Wn[k][2l..])}
    __shared__ ull        sBuf[8][2][128]; // 16KB : per-warp h-dup[0..63], agg-dup[64..127]

    int t = threadIdx.x;
    int w = t >> 5, lane = t & 31;

    for (int i = t; i < 2048; i += 256) {
        int k = i >> 5, l = i & 31;
        float2 ws = __ldg((const float2*)(Ws + k * 64) + l);
        float2 wn = __ldg((const float2*)(Wn + k * 64) + l);
        ulonglong2 v;
        v.x = pack2(ws.x, ws.y);
        v.y = pack2(wn.x, wn.y);
        sW4[k][l] = v;
    }
    __syncthreads();

    float2 b2 = __ldg((const float2*)bb + lane);
    ull bias_u = pack2(b2.x, b2.y);

    const float* __restrict__ Hin = mode ? g_H1 : g_H0;
    int gwarp = blockIdx.x * 8 + w;
    int nWarps = gridDim.x * 8;

    for (int gi = gwarp; gi < numGroups; gi += nWarps) {
        int base = gi * 2;

        // stage h + agg (duplicated)
        #pragma unroll
        for (int m = 0; m < 2; m++) {
            int n = base + m;
            float2 h2 = make_float2(0.f, 0.f), a2 = make_float2(0.f, 0.f);
            if (n < NN) {
                h2 = __ldg((const float2*)(Hin + (size_t)n * 64) + lane);
                a2 = *((const float2*)(g_AGG + (size_t)n * 64) + lane);
                if (mode == 0)
                    *((float2*)(g_AGG + (size_t)n * 64) + lane) = make_float2(0.f, 0.f);
            }
            ulonglong2 hv;
            hv.x = pack2(h2.x, h2.x);
            hv.y = pack2(h2.y, h2.y);
            *(ulonglong2*)&sBuf[w][m][2 * lane] = hv;
            ulonglong2 av;
            av.x = pack2(a2.x, a2.x);
            av.y = pack2(a2.y, a2.y);
            *(ulonglong2*)&sBuf[w][m][64 + 2 * lane] = av;
        }
        __syncwarp();

        ull acc0 = bias_u, acc1 = bias_u;
        #pragma unroll 8
        for (int k = 0; k < 64; k++) {
            ulonglong2 w4 = sW4[k][lane];
            ull wsp = w4.x, wnp = w4.y;
            fma2(acc0, sBuf[w][0][k], wsp);
            fma2(acc0, sBuf[w][0][64 + k], wnp);
            fma2(acc1, sBuf[w][1][k], wsp);
            fma2(acc1, sBuf[w][1][64 + k], wnp);
        }

        #pragma unroll
        for (int m = 0; m < 2; m++) {
            int n = base + m;
            if (n >= NN) continue;
            float2 r = unpack2(m == 0 ? acc0 : acc1);
            r.x = fmaxf(r.x, 0.f);
            r.y = fmaxf(r.y, 0.f);
            if (mode == 0) {
                *((float2*)(g_H1 + (size_t)n * 64) + lane) = r;
            } else {
                float2 xv = __ldg((const float2*)(g_X + (size_t)n * 64) + lane);
                r.x += xv.x; r.y += xv.y;
                *((float2*)(out + (size_t)n * 64) + lane) = r;
                if (dup)
                    *((float2*)(out + (size_t)(NN + n) * 64) + lane) = r;
            }
        }
        __syncwarp();
    }
}

// ---------------------------------------------------------------------------
// kernel_launch
// ---------------------------------------------------------------------------
extern "C" void kernel_launch(void* const* d_in, const int* in_sizes, int n_in,
                              void* d_out, int out_size)
{
    const void*  ei     = d_in[0];
    const void*  ti     = d_in[2];
    const float* user   = (const float*)d_in[3];
    const float* item   = (const float*)d_in[4];
    const float* te     = (const float*)d_in[5];
    const float* causal = (const float*)d_in[6];
    const float* Wq = (const float*)d_in[7],  *bq = (const float*)d_in[8];
    const float* Wk = (const float*)d_in[9],  *bk = (const float*)d_in[10];
    const float* Wv = (const float*)d_in[11], *bv = (const float*)d_in[12];
    const float* Wo = (const float*)d_in[13], *bo = (const float*)d_in[14];
    const float* Ws0 = (const float*)d_in[15], *Wn0 = (const float*)d_in[16];
    const float* b0  = (const float*)d_in[17];
    const float* Ws1 = (const float*)d_in[18], *Wn1 = (const float*)d_in[19];
    const float* b1  = (const float*)d_in[20];

    int E = in_sizes[1];
    float* out = (float*)d_out;
    int dup = (out_size >= 2 * NN * 64) ? 1 : 0;

    int groups4 = (NN + 3) / 4;   // 37500
    int groups2 = (NN + 1) / 2;   // 75000
    int scatBlocks = (E + 15) / 16;

    precompute_kernel<<<4, 256>>>(te, Wq, bq, Wk, bk, Wv, bv, Wo, ei, ti);
    node_kernel<<<1184, 256>>>(user, item, ti, te, bo, causal, groups4);
    scatter_kernel<<<scatBlocks, 256>>>(ei, E, 0);
    dense_kernel<<<1184, 256>>>(Ws0, Wn0, b0, nullptr, 0, groups2, 0);
    scatter_kernel<<<scatBlocks, 256>>>(ei, E, 1);
    dense_kernel<<<1184, 256>>>(Ws1, Wn1, b1, out, dup, groups2, 1);
}

// round 9
// speedup vs baseline: 1.4808x; 1.4808x over previous
#include <cuda_runtime.h>
#include <cstdint>

#define NU 100000
#define NI 50000
#define NN 150000
#define MAXE 2400000
#define NB 586                 // ceil(NN/256) ; 586*256 = 150016

// ---------------------------------------------------------------------------
// Device-global scratch
// ---------------------------------------------------------------------------
__device__ float g_P[32 * 64];      // P[i=h*8+t][j] : score projection (scaled by 1/4)
__device__ float g_C[8 * 32];       // C[t0][i]
__device__ float g_WvWo[64 * 64];   // Wv @ Wo
__device__ float g_VoffO[32 * 64];  // VoffO[i][j]
__device__ int   g_ei64;
__device__ int   g_ti64;

__device__ float g_X[(size_t)NN * 64];
__device__ float g_H0[(size_t)NN * 64];
__device__ float g_H1[(size_t)NN * 64];
__device__ float g_AGG[(size_t)NN * 64];

// CSR structures (built once per call, reused for both layers)
__device__ int g_deg[NB * 256];
__device__ int g_start[NB * 256];
__device__ int g_cursor[NB * 256];
__device__ int g_bsum[1024];
__device__ int g_csr[MAXE];

// ---------------------------------------------------------------------------
// Kernel 1: precompute, 4 blocks (proven R5 form)
// ---------------------------------------------------------------------------
__global__ void __launch_bounds__(256) precompute_kernel(
    const float* __restrict__ te,
    const float* __restrict__ Wq, const float* __restrict__ bq,
    const float* __restrict__ Wk, const float* __restrict__ bk,
    const float* __restrict__ Wv, const float* __restrict__ bv,
    const float* __restrict__ Wo,
    const void* __restrict__ ei_raw, const void* __restrict__ ti_raw)
{
    __shared__ float qoff[512], koff[512], voff[512];
    __shared__ float sWo[4096];
    int t = threadIdx.x;
    int blk = blockIdx.x;

    for (int idx = t; idx < 512; idx += 256) {
        int tt = idx >> 6, d = idx & 63;
        float q = bq[d], k = bk[d], v = bv[d];
        for (int j = 0; j < 64; j++) {
            float x = __ldg(te + tt * 64 + j);
            q += x * __ldg(Wq + j * 64 + d);
            k += x * __ldg(Wk + j * 64 + d);
            v += x * __ldg(Wv + j * 64 + d);
        }
        qoff[idx] = q; koff[idx] = k; voff[idx] = v;
    }
    if (blk >= 1) {
        for (int i = t; i < 4096; i += 256) sWo[i] = __ldg(Wo + i);
    }
    __syncthreads();

    if (blk == 0) {
        // P[i][j] (row-major as in R3), pre-scaled by 1/sqrt(16)
        for (int idx = t; idx < 2048; idx += 256) {
            int i = idx >> 6, j = idx & 63;
            int h = i >> 3, tt = i & 7;
            float s = 0.f;
            #pragma unroll
            for (int m = 0; m < 16; m++)
                s += __ldg(Wq + j * 64 + h * 16 + m) * koff[tt * 64 + h * 16 + m];
            g_P[idx] = 0.25f * s;
        }
        for (int idx = t; idx < 256; idx += 256) {
            int t0 = idx >> 5, i = idx & 31;
            int h = i >> 3, tt = i & 7;
            float s = 0.f;
            #pragma unroll
            for (int m = 0; m < 16; m++)
                s += qoff[t0 * 64 + h * 16 + m] * koff[tt * 64 + h * 16 + m];
            g_C[idx] = 0.25f * s;
        }
        if (t == 0) {
            const int* e32 = (const int*)ei_raw;
            const int* t32 = (const int*)ti_raw;
            int is64 = 1;
            for (int i = 0; i < 64; i++) if (e32[2 * i + 1] != 0) { is64 = 0; break; }
            g_ei64 = is64;
            is64 = 1;
            for (int i = 0; i < 64; i++) if (t32[2 * i + 1] != 0) { is64 = 0; break; }
            g_ti64 = is64;
        }
    } else if (blk == 1) {
        for (int idx = t; idx < 2048; idx += 256) {
            int i = idx >> 6, j = idx & 63;
            int h = i >> 3, tt = i & 7;
            float s = 0.f;
            #pragma unroll
            for (int m = 0; m < 16; m++)
                s += voff[tt * 64 + h * 16 + m] * sWo[(h * 16 + m) * 64 + j];
            g_VoffO[idx] = s;
        }
    } else {
        int kbase = (blk - 2) * 32;
        int k = kbase + (t >> 3);
        int j0 = (t & 7) * 8;
        float xv[64];
        #pragma unroll 16
        for (int d = 0; d < 64; d++) xv[d] = __ldg(Wv + k * 64 + d);
        float acc[8];
        #pragma unroll
        for (int j = 0; j < 8; j++) acc[j] = 0.f;
        for (int d = 0; d < 64; d++) {
            float x = xv[d];
            #pragma unroll
            for (int j = 0; j < 8; j++) acc[j] += x * sWo[d * 64 + j0 + j];
        }
        #pragma unroll
        for (int j = 0; j < 8; j++) g_WvWo[k * 64 + j0 + j] = acc[j];
    }
}

// ---------------------------------------------------------------------------
// CSR build kernels
// ---------------------------------------------------------------------------
__global__ void __launch_bounds__(256) k_zero_deg()
{
    int n = blockIdx.x * 256 + threadIdx.x;
    g_deg[n] = 0;
}

__global__ void __launch_bounds__(256) k_count(const void* __restrict__ ei_raw, int E)
{
    int e = blockIdx.x * 256 + threadIdx.x;
    if (e >= E) return;
    int dst;
    if (g_ei64) dst = (int)((const long long*)ei_raw)[(size_t)E + e];
    else        dst = ((const int*)ei_raw)[(size_t)E + e];
    atomicAdd(&g_deg[dst], 1);
}

__global__ void __launch_bounds__(256) k_bsum()
{
    __shared__ int sd[256];
    int t = threadIdx.x;
    sd[t] = g_deg[blockIdx.x * 256 + t];
    __syncthreads();
    for (int off = 128; off > 0; off >>= 1) {
        if (t < off) sd[t] += sd[t + off];
        __syncthreads();
    }
    if (t == 0) g_bsum[blockIdx.x] = sd[0];
}

__global__ void __launch_bounds__(1024) k_scan()
{
    __shared__ int sd[1024];
    int t = threadIdx.x;
    int v = (t < NB) ? g_bsum[t] : 0;
    sd[t] = v;
    __syncthreads();
    for (int off = 1; off < 1024; off <<= 1) {
        int u = (t >= off) ? sd[t - off] : 0;
        __syncthreads();
        sd[t] += u;
        __syncthreads();
    }
    if (t < NB) g_bsum[t] = sd[t] - v;   // exclusive
}

__global__ void __launch_bounds__(256) k_offsets()
{
    __shared__ int sd[256];
    int t = threadIdx.x;
    int n = blockIdx.x * 256 + t;
    int v = g_deg[n];
    sd[t] = v;
    __syncthreads();
    for (int off = 1; off < 256; off <<= 1) {
        int u = (t >= off) ? sd[t - off] : 0;
        __syncthreads();
        sd[t] += u;
        __syncthreads();
    }
    int start = g_bsum[blockIdx.x] + sd[t] - v;
    g_start[n] = start;
    g_cursor[n] = start;
}

__global__ void __launch_bounds__(256) k_fill(const void* __restrict__ ei_raw, int E)
{
    int e = blockIdx.x * 256 + threadIdx.x;
    if (e >= E) return;
    int src, dst;
    if (g_ei64) {
        const long long* p = (const long long*)ei_raw;
        src = (int)p[e];
        dst = (int)p[(size_t)E + e];
    } else {
        const int* p = (const int*)ei_raw;
        src = p[e];
        dst = p[(size_t)E + e];
    }
    int slot = atomicAdd(&g_cursor[dst], 1);
    g_csr[slot] = src;
}

// ---------------------------------------------------------------------------
// Gather kernel: warp per node, CSR neighbor-sum (replaces atomic scatter).
// mode 0: sum rows of g_H0 -> g_AGG ; mode 1: sum rows of g_H1 -> g_AGG
// ---------------------------------------------------------------------------
__global__ void __launch_bounds__(256) gather_kernel(int mode)
{
    const float* __restrict__ H = mode ? g_H1 : g_H0;
    int n = blockIdx.x * 8 + (threadIdx.x >> 5);
    int lane = threadIdx.x & 31;
    if (n >= NN) return;

    int s = g_start[n];
    int d = g_deg[n];
    int end = s + d;
    float2 acc = make_float2(0.f, 0.f);

    int j = s;
    for (; j + 3 < end; j += 4) {
        int i0 = __ldg(g_csr + j);
        int i1 = __ldg(g_csr + j + 1);
        int i2 = __ldg(g_csr + j + 2);
        int i3 = __ldg(g_csr + j + 3);
        float2 v0 = __ldg((const float2*)(H + (size_t)i0 * 64) + lane);
        float2 v1 = __ldg((const float2*)(H + (size_t)i1 * 64) + lane);
        float2 v2 = __ldg((const float2*)(H + (size_t)i2 * 64) + lane);
        float2 v3 = __ldg((const float2*)(H + (size_t)i3 * 64) + lane);
        acc.x += v0.x + v1.x + v2.x + v3.x;
        acc.y += v0.y + v1.y + v2.y + v3.y;
    }
    for (; j < end; j++) {
        int i0 = __ldg(g_csr + j);
        float2 v0 = __ldg((const float2*)(H + (size_t)i0 * 64) + lane);
        acc.x += v0.x;
        acc.y += v0.y;
    }
    *((float2*)(g_AGG + (size_t)n * 64) + lane) = acc;
}

// ---------------------------------------------------------------------------
// node kernel — R3 proven form (warp per 4 nodes, persistent grid).
// ---------------------------------------------------------------------------
__device__ __forceinline__ float softmax8(float s)
{
    const unsigned FULL = 0xffffffffu;
    float m = fmaxf(s, __shfl_xor_sync(FULL, s, 1));
    m = fmaxf(m, __shfl_xor_sync(FULL, m, 2));
    m = fmaxf(m, __shfl_xor_sync(FULL, m, 4));
    float e = __expf(s - m);
    float t = e + __shfl_xor_sync(FULL, e, 1);
    t += __shfl_xor_sync(FULL, t, 2);
    t += __shfl_xor_sync(FULL, t, 4);
    return e / t;
}

__global__ void __launch_bounds__(256) node_kernel(
    const float* __restrict__ user_emb,
    const float* __restrict__ item_emb,
    const void* __restrict__ ti_raw,
    const float* __restrict__ te,
    const float* __restrict__ bo,
    const float* __restrict__ causal,
    int numTiles)
{
    __shared__ float sP[32 * 65];
    __shared__ float sW[64 * 64];
    __shared__ float sVO[32 * 64];
    __shared__ float sC[256];
    __shared__ float sTE[8 * 64];
    __shared__ float sBO[64];
    __shared__ float sX[8][4][64];

    int tid = threadIdx.x;
    for (int idx = tid; idx < 32 * 64; idx += 256) {
        sP[(idx >> 6) * 65 + (idx & 63)] = g_P[idx];
        sVO[idx] = g_VoffO[idx];
    }
    for (int idx = tid; idx < 64 * 64; idx += 256) sW[idx] = g_WvWo[idx];
    if (tid < 256) sC[tid] = g_C[tid];
    for (int idx = tid; idx < 512; idx += 256) sTE[idx] = te[idx];
    if (tid < 64) sBO[tid] = bo[tid];
    int ti64 = g_ti64;
    __syncthreads();

    int w = tid >> 5, lane = tid & 31;
    const long long* tp64 = (const long long*)ti_raw;
    const int*       tp32 = (const int*)ti_raw;
    const unsigned FULL = 0xffffffffu;

    float* x0 = &sX[w][0][0];
    float* x1 = &sX[w][1][0];
    float* x2 = &sX[w][2][0];
    float* x3 = &sX[w][3][0];

    for (int tile = blockIdx.x; tile < numTiles; tile += gridDim.x) {
        int base = tile * 32 + w * 4;
        int t0a = 0, t0b = 0, t0c = 0, t0d = 0;

        #pragma unroll
        for (int m = 0; m < 4; m++) {
            int n = base + m;
            float2 xv = make_float2(0.f, 0.f);
            int tt = 0;
            if (n < NN) {
                const float* src = (n < NU) ? (user_emb + (size_t)n * 64)
                                            : (item_emb + (size_t)(n - NU) * 64);
                xv = ((const float2*)src)[lane];
                tt = ti64 ? (int)tp64[n] : tp32[n];
            }
            sX[w][m][2 * lane]     = xv.x;
            sX[w][m][2 * lane + 1] = xv.y;
            if (m == 0) t0a = tt; else if (m == 1) t0b = tt;
            else if (m == 2) t0c = tt; else t0d = tt;
        }
        __syncwarp();

        float s0 = 0.f, s1 = 0.f, s2 = 0.f, s3 = 0.f;
        const float* pr = sP + lane * 65;
        #pragma unroll 8
        for (int j = 0; j < 64; j++) {
            float p = pr[j];
            s0 += p * x0[j]; s1 += p * x1[j];
            s2 += p * x2[j]; s3 += p * x3[j];
        }
        s0 += sC[t0a * 32 + lane];
        s1 += sC[t0b * 32 + lane];
        s2 += sC[t0c * 32 + lane];
        s3 += sC[t0d * 32 + lane];

        float a0 = softmax8(s0);
        float a1 = softmax8(s1);
        float a2 = softmax8(s2);
        float a3 = softmax8(s3);

        float bx = sBO[2 * lane], by = sBO[2 * lane + 1];
        float2 acc0, acc1, acc2, acc3;
        acc0.x = bx + sTE[t0a * 64 + 2 * lane]     + x0[2 * lane];
        acc0.y = by + sTE[t0a * 64 + 2 * lane + 1] + x0[2 * lane + 1];
        acc1.x = bx + sTE[t0b * 64 + 2 * lane]     + x1[2 * lane];
        acc1.y = by + sTE[t0b * 64 + 2 * lane + 1] + x1[2 * lane + 1];
        acc2.x = bx + sTE[t0c * 64 + 2 * lane]     + x2[2 * lane];
        acc2.y = by + sTE[t0c * 64 + 2 * lane + 1] + x2[2 * lane + 1];
        acc3.x = bx + sTE[t0d * 64 + 2 * lane]     + x3[2 * lane];
        acc3.y = by + sTE[t0d * 64 + 2 * lane + 1] + x3[2 * lane + 1];

        #pragma unroll 8
        for (int i = 0; i < 32; i++) {
            float2 v = *(const float2*)(sVO + i * 64 + 2 * lane);
            float b0 = __shfl_sync(FULL, a0, i);
            float b1 = __shfl_sync(FULL, a1, i);
            float b2 = __shfl_sync(FULL, a2, i);
            float b3 = __shfl_sync(FULL, a3, i);
            acc0.x += b0 * v.x; acc0.y += b0 * v.y;
            acc1.x += b1 * v.x; acc1.y += b1 * v.y;
            acc2.x += b2 * v.x; acc2.y += b2 * v.y;
            acc3.x += b3 * v.x; acc3.y += b3 * v.y;
        }

        #pragma unroll 8
        for (int k = 0; k < 64; k++) {
            float2 v = *(const float2*)(sW + k * 64 + 2 * lane);
            float h0 = x0[k], h1 = x1[k], h2 = x2[k], h3 = x3[k];
            acc0.x += h0 * v.x; acc0.y += h0 * v.y;
            acc1.x += h1 * v.x; acc1.y += h1 * v.y;
            acc2.x += h2 * v.x; acc2.y += h2 * v.y;
            acc3.x += h3 * v.x; acc3.y += h3 * v.y;
        }

        #pragma unroll
        for (int m = 0; m < 4; m++) {
            int n = base + m;
            if (n >= NN) continue;
            float2 r = (m == 0) ? acc0 : (m == 1) ? acc1 : (m == 2) ? acc2 : acc3;
            float2 c = ((const float2*)(causal + (size_t)n * 64))[lane];
            ((float2*)(g_X + (size_t)n * 64))[lane] = r;
            float2 h;
            h.x = r.x + 0.5f * c.x;
            h.y = r.y + 0.5f * c.y;
            ((float2*)(g_H0 + (size_t)n * 64))[lane] = h;
        }
        __syncwarp();
    }
}

// ---------------------------------------------------------------------------
// dense kernel — R3 proven form (warp per 2 nodes, persistent grid).
// ---------------------------------------------------------------------------
__global__ void __launch_bounds__(256) dense_kernel(
    const float* __restrict__ Ws, const float* __restrict__ Wn,
    const float* __restrict__ bb,
    float* __restrict__ out, int dup, int numTiles, int mode)
{
    __shared__ float sWs[64 * 64];
    __shared__ float sWn[64 * 64];
    __shared__ float sB[64];
    __shared__ float sV[8][2][128];

    int tid = threadIdx.x;
    for (int idx = tid; idx < 64 * 64; idx += 256) {
        sWs[idx] = Ws[idx];
        sWn[idx] = Wn[idx];
    }
    if (tid < 64) sB[tid] = bb[tid];
    __syncthreads();

    int w = tid >> 5, lane = tid & 31;
    const float* __restrict__ Hin = mode ? g_H1 : g_H0;

    for (int tile = blockIdx.x; tile < numTiles; tile += gridDim.x) {
        int base = tile * 16 + w * 2;

        #pragma unroll
        for (int m = 0; m < 2; m++) {
            int n = base + m;
            float2 h = make_float2(0.f, 0.f), a = make_float2(0.f, 0.f);
            if (n < NN) {
                h = ((const float2*)(Hin + (size_t)n * 64))[lane];
                a = ((const float2*)(g_AGG + (size_t)n * 64))[lane];
            }
            sV[w][m][2 * lane]       = h.x;
            sV[w][m][2 * lane + 1]   = h.y;
            sV[w][m][64 + 2 * lane]     = a.x;
            sV[w][m][64 + 2 * lane + 1] = a.y;
        }
        __syncwarp();

        float2 acc0, acc1;
        acc0.x = acc1.x = sB[2 * lane];
        acc0.y = acc1.y = sB[2 * lane + 1];

        const float* v0 = &sV[w][0][0];
        const float* v1 = &sV[w][1][0];
        #pragma unroll 8
        for (int k = 0; k < 64; k++) {
            float2 ws = *(const float2*)(sWs + k * 64 + 2 * lane);
            float2 wn = *(const float2*)(sWn + k * 64 + 2 * lane);
            float h0 = v0[k], a0 = v0[64 + k];
            float h1 = v1[k], a1 = v1[64 + k];
            acc0.x += h0 * ws.x + a0 * wn.x;
            acc0.y += h0 * ws.y + a0 * wn.y;
            acc1.x += h1 * ws.x + a1 * wn.x;
            acc1.y += h1 * ws.y + a1 * wn.y;
        }

        #pragma unroll
        for (int m = 0; m < 2; m++) {
            int n = base + m;
            if (n >= NN) continue;
            float2 acc = (m == 0) ? acc0 : acc1;
            float rx = fmaxf(acc.x, 0.f);
            float ry = fmaxf(acc.y, 0.f);
            if (mode == 0) {
                float2 r = make_float2(rx, ry);
                ((float2*)(g_H1 + (size_t)n * 64))[lane] = r;
            } else {
                float2 xv = ((const float2*)(g_X + (size_t)n * 64))[lane];
                float2 r = make_float2(xv.x + rx, xv.y + ry);
                ((float2*)(out + (size_t)n * 64))[lane] = r;
                if (dup)
                    ((float2*)(out + (size_t)(NN + n) * 64))[lane] = r;
            }
        }
        __syncwarp();
    }
}

// ---------------------------------------------------------------------------
// kernel_launch
// ---------------------------------------------------------------------------
extern "C" void kernel_launch(void* const* d_in, const int* in_sizes, int n_in,
                              void* d_out, int out_size)
{
    const void*  ei     = d_in[0];
    const void*  ti     = d_in[2];
    const float* user   = (const float*)d_in[3];
    const float* item   = (const float*)d_in[4];
    const float* te     = (const float*)d_in[5];
    const float* causal = (const float*)d_in[6];
    const float* Wq = (const float*)d_in[7],  *bq = (const float*)d_in[8];
    const float* Wk = (const float*)d_in[9],  *bk = (const float*)d_in[10];
    const float* Wv = (const float*)d_in[11], *bv = (const float*)d_in[12];
    const float* Wo = (const float*)d_in[13], *bo = (const float*)d_in[14];
    const float* Ws0 = (const float*)d_in[15], *Wn0 = (const float*)d_in[16];
    const float* b0  = (const float*)d_in[17];
    const float* Ws1 = (const float*)d_in[18], *Wn1 = (const float*)d_in[19];
    const float* b1  = (const float*)d_in[20];

    int E = in_sizes[1];
    if (E > MAXE) E = MAXE;
    float* out = (float*)d_out;
    int dup = (out_size >= 2 * NN * 64) ? 1 : 0;

    int nodeTiles  = (NN + 31) / 32;      // 4688
    int denseTiles = (NN + 15) / 16;      // 9375
    int edgeBlocks = (E + 255) / 256;     // 9375
    int gatherBlocks = (NN + 7) / 8;      // 18750

    precompute_kernel<<<4, 256>>>(te, Wq, bq, Wk, bk, Wv, bv, Wo, ei, ti);

    // CSR build (uses g_ei64 set by precompute; stream-ordered)
    k_zero_deg<<<NB, 256>>>();
    k_count<<<edgeBlocks, 256>>>(ei, E);
    k_bsum<<<NB, 256>>>();
    k_scan<<<1, 1024>>>();
    k_offsets<<<NB, 256>>>();
    k_fill<<<edgeBlocks, 256>>>(ei, E);

    node_kernel<<<1184, 256>>>(user, item, ti, te, bo, causal, nodeTiles);
    gather_kernel<<<gatherBlocks, 256>>>(0);
    dense_kernel<<<1184, 256>>>(Ws0, Wn0, b0, nullptr, 0, denseTiles, 0);
    gather_kernel<<<gatherBlocks, 256>>>(1);
    dense_kernel<<<1184, 256>>>(Ws1, Wn1, b1, out, dup, denseTiles, 1);
}

// round 10
// speedup vs baseline: 1.5159x; 1.0237x over previous
#include <cuda_runtime.h>
#include <cstdint>

#define NU 100000
#define NI 50000
#define NN 150000
#define MAXE 2400000
#define NB 586                 // ceil(NN/256) ; 586*256 = 150016

// ---------------------------------------------------------------------------
// Device-global scratch
// ---------------------------------------------------------------------------
__device__ float g_P[32 * 64];      // P[i=h*8+t][j] : score projection (scaled by 1/4)
__device__ float g_C[8 * 32];       // C[t0][i]
__device__ float g_WvWo[64 * 64];   // Wv @ Wo
__device__ float g_VoffO[32 * 64];  // VoffO[i][j]
__device__ int   g_ei64;
__device__ int   g_ti64;

__device__ float g_X[(size_t)NN * 64];
__device__ float g_H0[(size_t)NN * 64];
__device__ float g_H1[(size_t)NN * 64];

// CSR structures (built once per call, reused for both layers)
__device__ int g_deg[NB * 256];
__device__ int g_start[NB * 256];
__device__ int g_cursor[NB * 256];
__device__ int g_bsum[1024];
__device__ int g_csr[MAXE];

// ---------------------------------------------------------------------------
// Kernel 1: precompute (blocks 0-3) + deg zeroing (blocks 4..NB+3)
// ---------------------------------------------------------------------------
__global__ void __launch_bounds__(256) precompute_kernel(
    const float* __restrict__ te,
    const float* __restrict__ Wq, const float* __restrict__ bq,
    const float* __restrict__ Wk, const float* __restrict__ bk,
    const float* __restrict__ Wv, const float* __restrict__ bv,
    const float* __restrict__ Wo,
    const void* __restrict__ ei_raw, const void* __restrict__ ti_raw)
{
    int t = threadIdx.x;
    int blk = blockIdx.x;

    if (blk >= 4) {                 // deg zeroing
        g_deg[(blk - 4) * 256 + t] = 0;
        return;
    }

    __shared__ float qoff[512], koff[512], voff[512];
    __shared__ float sWo[4096];

    for (int idx = t; idx < 512; idx += 256) {
        int tt = idx >> 6, d = idx & 63;
        float q = bq[d], k = bk[d], v = bv[d];
        for (int j = 0; j < 64; j++) {
            float x = __ldg(te + tt * 64 + j);
            q += x * __ldg(Wq + j * 64 + d);
            k += x * __ldg(Wk + j * 64 + d);
            v += x * __ldg(Wv + j * 64 + d);
        }
        qoff[idx] = q; koff[idx] = k; voff[idx] = v;
    }
    if (blk >= 1) {
        for (int i = t; i < 4096; i += 256) sWo[i] = __ldg(Wo + i);
    }
    __syncthreads();

    if (blk == 0) {
        for (int idx = t; idx < 2048; idx += 256) {
            int i = idx >> 6, j = idx & 63;
            int h = i >> 3, tt = i & 7;
            float s = 0.f;
            #pragma unroll
            for (int m = 0; m < 16; m++)
                s += __ldg(Wq + j * 64 + h * 16 + m) * koff[tt * 64 + h * 16 + m];
            g_P[idx] = 0.25f * s;
        }
        for (int idx = t; idx < 256; idx += 256) {
            int t0 = idx >> 5, i = idx & 31;
            int h = i >> 3, tt = i & 7;
            float s = 0.f;
            #pragma unroll
            for (int m = 0; m < 16; m++)
                s += qoff[t0 * 64 + h * 16 + m] * koff[tt * 64 + h * 16 + m];
            g_C[idx] = 0.25f * s;
        }
        if (t == 0) {
            const int* e32 = (const int*)ei_raw;
            const int* t32 = (const int*)ti_raw;
            int is64 = 1;
            for (int i = 0; i < 64; i++) if (e32[2 * i + 1] != 0) { is64 = 0; break; }
            g_ei64 = is64;
            is64 = 1;
            for (int i = 0; i < 64; i++) if (t32[2 * i + 1] != 0) { is64 = 0; break; }
            g_ti64 = is64;
        }
    } else if (blk == 1) {
        for (int idx = t; idx < 2048; idx += 256) {
            int i = idx >> 6, j = idx & 63;
            int h = i >> 3, tt = i & 7;
            float s = 0.f;
            #pragma unroll
            for (int m = 0; m < 16; m++)
                s += voff[tt * 64 + h * 16 + m] * sWo[(h * 16 + m) * 64 + j];
            g_VoffO[idx] = s;
        }
    } else {
        int kbase = (blk - 2) * 32;
        int k = kbase + (t >> 3);
        int j0 = (t & 7) * 8;
        float xv[64];
        #pragma unroll 16
        for (int d = 0; d < 64; d++) xv[d] = __ldg(Wv + k * 64 + d);
        float acc[8];
        #pragma unroll
        for (int j = 0; j < 8; j++) acc[j] = 0.f;
        for (int d = 0; d < 64; d++) {
            float x = xv[d];
            #pragma unroll
            for (int j = 0; j < 8; j++) acc[j] += x * sWo[d * 64 + j0 + j];
        }
        #pragma unroll
        for (int j = 0; j < 8; j++) g_WvWo[k * 64 + j0 + j] = acc[j];
    }
}

// ---------------------------------------------------------------------------
// CSR build kernels
// ---------------------------------------------------------------------------
__global__ void __launch_bounds__(256) k_count(const void* __restrict__ ei_raw, int E)
{
    int e = blockIdx.x * 256 + threadIdx.x;
    if (e >= E) return;
    int dst;
    if (g_ei64) dst = (int)((const long long*)ei_raw)[(size_t)E + e];
    else        dst = ((const int*)ei_raw)[(size_t)E + e];
    atomicAdd(&g_deg[dst], 1);
}

__global__ void __launch_bounds__(256) k_bsum()
{
    __shared__ int sd[256];
    int t = threadIdx.x;
    sd[t] = g_deg[blockIdx.x * 256 + t];
    __syncthreads();
    for (int off = 128; off > 0; off >>= 1) {
        if (t < off) sd[t] += sd[t + off];
        __syncthreads();
    }
    if (t == 0) g_bsum[blockIdx.x] = sd[0];
}

__global__ void __launch_bounds__(1024) k_scan()
{
    __shared__ int sd[1024];
    int t = threadIdx.x;
    int v = (t < NB) ? g_bsum[t] : 0;
    sd[t] = v;
    __syncthreads();
    for (int off = 1; off < 1024; off <<= 1) {
        int u = (t >= off) ? sd[t - off] : 0;
        __syncthreads();
        sd[t] += u;
        __syncthreads();
    }
    if (t < NB) g_bsum[t] = sd[t] - v;   // exclusive
}

__global__ void __launch_bounds__(256) k_offsets()
{
    __shared__ int sd[256];
    int t = threadIdx.x;
    int n = blockIdx.x * 256 + t;
    int v = g_deg[n];
    sd[t] = v;
    __syncthreads();
    for (int off = 1; off < 256; off <<= 1) {
        int u = (t >= off) ? sd[t - off] : 0;
        __syncthreads();
        sd[t] += u;
        __syncthreads();
    }
    int start = g_bsum[blockIdx.x] + sd[t] - v;
    g_start[n] = start;
    g_cursor[n] = start;
}

__global__ void __launch_bounds__(256) k_fill(const void* __restrict__ ei_raw, int E)
{
    int e = blockIdx.x * 256 + threadIdx.x;
    if (e >= E) return;
    int src, dst;
    if (g_ei64) {
        const long long* p = (const long long*)ei_raw;
        src = (int)p[e];
        dst = (int)p[(size_t)E + e];
    } else {
        const int* p = (const int*)ei_raw;
        src = p[e];
        dst = p[(size_t)E + e];
    }
    int slot = atomicAdd(&g_cursor[dst], 1);
    g_csr[slot] = src;
}

// ---------------------------------------------------------------------------
// node kernel — R3 proven form (warp per 4 nodes, persistent grid).
// ---------------------------------------------------------------------------
__device__ __forceinline__ float softmax8(float s)
{
    const unsigned FULL = 0xffffffffu;
    float m = fmaxf(s, __shfl_xor_sync(FULL, s, 1));
    m = fmaxf(m, __shfl_xor_sync(FULL, m, 2));
    m = fmaxf(m, __shfl_xor_sync(FULL, m, 4));
    float e = __expf(s - m);
    float t = e + __shfl_xor_sync(FULL, e, 1);
    t += __shfl_xor_sync(FULL, t, 2);
    t += __shfl_xor_sync(FULL, t, 4);
    return e / t;
}

__global__ void __launch_bounds__(256) node_kernel(
    const float* __restrict__ user_emb,
    const float* __restrict__ item_emb,
    const void* __restrict__ ti_raw,
    const float* __restrict__ te,
    const float* __restrict__ bo,
    const float* __restrict__ causal,
    int numTiles)
{
    __shared__ float sP[32 * 65];
    __shared__ float sW[64 * 64];
    __shared__ float sVO[32 * 64];
    __shared__ float sC[256];
    __shared__ float sTE[8 * 64];
    __shared__ float sBO[64];
    __shared__ float sX[8][4][64];

    int tid = threadIdx.x;
    for (int idx = tid; idx < 32 * 64; idx += 256) {
        sP[(idx >> 6) * 65 + (idx & 63)] = g_P[idx];
        sVO[idx] = g_VoffO[idx];
    }
    for (int idx = tid; idx < 64 * 64; idx += 256) sW[idx] = g_WvWo[idx];
    if (tid < 256) sC[tid] = g_C[tid];
    for (int idx = tid; idx < 512; idx += 256) sTE[idx] = te[idx];
    if (tid < 64) sBO[tid] = bo[tid];
    int ti64 = g_ti64;
    __syncthreads();

    int w = tid >> 5, lane = tid & 31;
    const long long* tp64 = (const long long*)ti_raw;
    const int*       tp32 = (const int*)ti_raw;
    const unsigned FULL = 0xffffffffu;

    float* x0 = &sX[w][0][0];
    float* x1 = &sX[w][1][0];
    float* x2 = &sX[w][2][0];
    float* x3 = &sX[w][3][0];

    for (int tile = blockIdx.x; tile < numTiles; tile += gridDim.x) {
        int base = tile * 32 + w * 4;
        int t0a = 0, t0b = 0, t0c = 0, t0d = 0;

        #pragma unroll
        for (int m = 0; m < 4; m++) {
            int n = base + m;
            float2 xv = make_float2(0.f, 0.f);
            int tt = 0;
            if (n < NN) {
                const float* src = (n < NU) ? (user_emb + (size_t)n * 64)
                                            : (item_emb + (size_t)(n - NU) * 64);
                xv = ((const float2*)src)[lane];
                tt = ti64 ? (int)tp64[n] : tp32[n];
            }
            sX[w][m][2 * lane]     = xv.x;
            sX[w][m][2 * lane + 1] = xv.y;
            if (m == 0) t0a = tt; else if (m == 1) t0b = tt;
            else if (m == 2) t0c = tt; else t0d = tt;
        }
        __syncwarp();

        float s0 = 0.f, s1 = 0.f, s2 = 0.f, s3 = 0.f;
        const float* pr = sP + lane * 65;
        #pragma unroll 8
        for (int j = 0; j < 64; j++) {
            float p = pr[j];
            s0 += p * x0[j]; s1 += p * x1[j];
            s2 += p * x2[j]; s3 += p * x3[j];
        }
        s0 += sC[t0a * 32 + lane];
        s1 += sC[t0b * 32 + lane];
        s2 += sC[t0c * 32 + lane];
        s3 += sC[t0d * 32 + lane];

        float a0 = softmax8(s0);
        float a1 = softmax8(s1);
        float a2 = softmax8(s2);
        float a3 = softmax8(s3);

        float bx = sBO[2 * lane], by = sBO[2 * lane + 1];
        float2 acc0, acc1, acc2, acc3;
        acc0.x = bx + sTE[t0a * 64 + 2 * lane]     + x0[2 * lane];
        acc0.y = by + sTE[t0a * 64 + 2 * lane + 1] + x0[2 * lane + 1];
        acc1.x = bx + sTE[t0b * 64 + 2 * lane]     + x1[2 * lane];
        acc1.y = by + sTE[t0b * 64 + 2 * lane + 1] + x1[2 * lane + 1];
        acc2.x = bx + sTE[t0c * 64 + 2 * lane]     + x2[2 * lane];
        acc2.y = by + sTE[t0c * 64 + 2 * lane + 1] + x2[2 * lane + 1];
        acc3.x = bx + sTE[t0d * 64 + 2 * lane]     + x3[2 * lane];
        acc3.y = by + sTE[t0d * 64 + 2 * lane + 1] + x3[2 * lane + 1];

        #pragma unroll 8
        for (int i = 0; i < 32; i++) {
            float2 v = *(const float2*)(sVO + i * 64 + 2 * lane);
            float b0 = __shfl_sync(FULL, a0, i);
            float b1 = __shfl_sync(FULL, a1, i);
            float b2 = __shfl_sync(FULL, a2, i);
            float b3 = __shfl_sync(FULL, a3, i);
            acc0.x += b0 * v.x; acc0.y += b0 * v.y;
            acc1.x += b1 * v.x; acc1.y += b1 * v.y;
            acc2.x += b2 * v.x; acc2.y += b2 * v.y;
            acc3.x += b3 * v.x; acc3.y += b3 * v.y;
        }

        #pragma unroll 8
        for (int k = 0; k < 64; k++) {
            float2 v = *(const float2*)(sW + k * 64 + 2 * lane);
            float h0 = x0[k], h1 = x1[k], h2 = x2[k], h3 = x3[k];
            acc0.x += h0 * v.x; acc0.y += h0 * v.y;
            acc1.x += h1 * v.x; acc1.y += h1 * v.y;
            acc2.x += h2 * v.x; acc2.y += h2 * v.y;
            acc3.x += h3 * v.x; acc3.y += h3 * v.y;
        }

        #pragma unroll
        for (int m = 0; m < 4; m++) {
            int n = base + m;
            if (n >= NN) continue;
            float2 r = (m == 0) ? acc0 : (m == 1) ? acc1 : (m == 2) ? acc2 : acc3;
            float2 c = ((const float2*)(causal + (size_t)n * 64))[lane];
            ((float2*)(g_X + (size_t)n * 64))[lane] = r;
            float2 h;
            h.x = r.x + 0.5f * c.x;
            h.y = r.y + 0.5f * c.y;
            ((float2*)(g_H0 + (size_t)n * 64))[lane] = h;
        }
        __syncwarp();
    }
}

// ---------------------------------------------------------------------------
// dense kernel — R3 proven GEMV form with the CSR gather FUSED into staging.
// Per node: agg = sum_{j in CSR[n]} H[j]  (L2-bound, hidden under smem GEMV)
// mode 0: relu(h0@Ws + agg@Wn + b) -> g_H1
// mode 1: out = g_X + relu(h1@Ws + agg@Wn + b)  (+ dup copy)
// ---------------------------------------------------------------------------
__global__ void __launch_bounds__(256) dense_kernel(
    const float* __restrict__ Ws, const float* __restrict__ Wn,
    const float* __restrict__ bb,
    float* __restrict__ out, int dup, int numTiles, int mode)
{
    __shared__ float sWs[64 * 64];
    __shared__ float sWn[64 * 64];
    __shared__ float sB[64];
    __shared__ float sV[8][2][128];

    int tid = threadIdx.x;
    for (int idx = tid; idx < 64 * 64; idx += 256) {
        sWs[idx] = Ws[idx];
        sWn[idx] = Wn[idx];
    }
    if (tid < 64) sB[tid] = bb[tid];
    __syncthreads();

    int w = tid >> 5, lane = tid & 31;
    const float* __restrict__ Hin = mode ? g_H1 : g_H0;

    for (int tile = blockIdx.x; tile < numTiles; tile += gridDim.x) {
        int base = tile * 16 + w * 2;

        #pragma unroll
        for (int m = 0; m < 2; m++) {
            int n = base + m;
            float2 h = make_float2(0.f, 0.f);
            float2 a = make_float2(0.f, 0.f);
            if (n < NN) {
                h = ((const float2*)(Hin + (size_t)n * 64))[lane];
                // fused CSR gather: agg = sum of neighbor rows of Hin
                int s = g_start[n];
                int end = s + g_deg[n];
                int j = s;
                for (; j + 3 < end; j += 4) {
                    int i0 = __ldg(g_csr + j);
                    int i1 = __ldg(g_csr + j + 1);
                    int i2 = __ldg(g_csr + j + 2);
                    int i3 = __ldg(g_csr + j + 3);
                    float2 v0 = __ldg((const float2*)(Hin + (size_t)i0 * 64) + lane);
                    float2 v1 = __ldg((const float2*)(Hin + (size_t)i1 * 64) + lane);
                    float2 v2 = __ldg((const float2*)(Hin + (size_t)i2 * 64) + lane);
                    float2 v3 = __ldg((const float2*)(Hin + (size_t)i3 * 64) + lane);
                    a.x += v0.x + v1.x + v2.x + v3.x;
                    a.y += v0.y + v1.y + v2.y + v3.y;
                }
                for (; j < end; j++) {
                    int i0 = __ldg(g_csr + j);
                    float2 v0 = __ldg((const float2*)(Hin + (size_t)i0 * 64) + lane);
                    a.x += v0.x;
                    a.y += v0.y;
                }
            }
            sV[w][m][2 * lane]          = h.x;
            sV[w][m][2 * lane + 1]      = h.y;
            sV[w][m][64 + 2 * lane]     = a.x;
            sV[w][m][64 + 2 * lane + 1] = a.y;
        }
        __syncwarp();

        float2 acc0, acc1;
        acc0.x = acc1.x = sB[2 * lane];
        acc0.y = acc1.y = sB[2 * lane + 1];

        const float* v0 = &sV[w][0][0];
        const float* v1 = &sV[w][1][0];
        #pragma unroll 8
        for (int k = 0; k < 64; k++) {
            float2 ws = *(const float2*)(sWs + k * 64 + 2 * lane);
            float2 wn = *(const float2*)(sWn + k * 64 + 2 * lane);
            float h0 = v0[k], a0 = v0[64 + k];
            float h1 = v1[k], a1 = v1[64 + k];
            acc0.x += h0 * ws.x + a0 * wn.x;
            acc0.y += h0 * ws.y + a0 * wn.y;
            acc1.x += h1 * ws.x + a1 * wn.x;
            acc1.y += h1 * ws.y + a1 * wn.y;
        }

        #pragma unroll
        for (int m = 0; m < 2; m++) {
            int n = base + m;
            if (n >= NN) continue;
            float2 acc = (m == 0) ? acc0 : acc1;
            float rx = fmaxf(acc.x, 0.f);
            float ry = fmaxf(acc.y, 0.f);
            if (mode == 0) {
                float2 r = make_float2(rx, ry);
                ((float2*)(g_H1 + (size_t)n * 64))[lane] = r;
            } else {
                float2 xv = ((const float2*)(g_X + (size_t)n * 64))[lane];
                float2 r = make_float2(xv.x + rx, xv.y + ry);
                ((float2*)(out + (size_t)n * 64))[lane] = r;
                if (dup)
                    ((float2*)(out + (size_t)(NN + n) * 64))[lane] = r;
            }
        }
        __syncwarp();
    }
}

// ---------------------------------------------------------------------------
// kernel_launch
// ---------------------------------------------------------------------------
extern "C" void kernel_launch(void* const* d_in, const int* in_sizes, int n_in,
                              void* d_out, int out_size)
{
    const void*  ei     = d_in[0];
    const void*  ti     = d_in[2];
    const float* user   = (const float*)d_in[3];
    const float* item   = (const float*)d_in[4];
    const float* te     = (const float*)d_in[5];
    const float* causal = (const float*)d_in[6];
    const float* Wq = (const float*)d_in[7],  *bq = (const float*)d_in[8];
    const float* Wk = (const float*)d_in[9],  *bk = (const float*)d_in[10];
    const float* Wv = (const float*)d_in[11], *bv = (const float*)d_in[12];
    const float* Wo = (const float*)d_in[13], *bo = (const float*)d_in[14];
    const float* Ws0 = (const float*)d_in[15], *Wn0 = (const float*)d_in[16];
    const float* b0  = (const float*)d_in[17];
    const float* Ws1 = (const float*)d_in[18], *Wn1 = (const float*)d_in[19];
    const float* b1  = (const float*)d_in[20];

    int E = in_sizes[1];
    if (E > MAXE) E = MAXE;
    float* out = (float*)d_out;
    int dup = (out_size >= 2 * NN * 64) ? 1 : 0;

    int nodeTiles  = (NN + 31) / 32;      // 4688
    int denseTiles = (NN + 15) / 16;      // 9375
    int edgeBlocks = (E + 255) / 256;     // 9375

    // precompute (blocks 0-3) + deg zeroing (blocks 4..NB+3)
    precompute_kernel<<<NB + 4, 256>>>(te, Wq, bq, Wk, bk, Wv, bv, Wo, ei, ti);

    // CSR build
    k_count<<<edgeBlocks, 256>>>(ei, E);
    k_bsum<<<NB, 256>>>();
    k_scan<<<1, 1024>>>();
    k_offsets<<<NB, 256>>>();
    k_fill<<<edgeBlocks, 256>>>(ei, E);

    node_kernel<<<1184, 256>>>(user, item, ti, te, bo, causal, nodeTiles);
    dense_kernel<<<1184, 256>>>(Ws0, Wn0, b0, nullptr, 0, denseTiles, 0);
    dense_kernel<<<1184, 256>>>(Ws1, Wn1, b1, out, dup, denseTiles, 1);
}

// round 11
// speedup vs baseline: 1.5398x; 1.0157x over previous
#include <cuda_runtime.h>
#include <cstdint>

#define NU 100000
#define NI 50000
#define NN 150000
#define MAXE 2400000
#define NB 586                 // ceil(NN/256) ; 586*256 = 150016

typedef unsigned long long ull;

__device__ __forceinline__ ull pack2(float x, float y) {
    ull r; asm("mov.b64 %0, {%1, %2};" : "=l"(r) : "f"(x), "f"(y)); return r;
}
__device__ __forceinline__ float2 unpack2(ull v) {
    float2 r; asm("mov.b64 {%0, %1}, %2;" : "=f"(r.x), "=f"(r.y) : "l"(v)); return r;
}
__device__ __forceinline__ void fma2(ull& d, ull a, ull b) {
    asm("fma.rn.f32x2 %0, %1, %2, %0;" : "+l"(d) : "l"(a), "l"(b));
}

// ---------------------------------------------------------------------------
// Device-global scratch
// ---------------------------------------------------------------------------
__device__ float g_P[32 * 64];      // P[i=h*8+t][j] : score projection (scaled by 1/4)
__device__ float g_C[8 * 32];       // C[t0][i]
__device__ float g_WvWo[64 * 64];   // Wv @ Wo
__device__ float g_VoffO[32 * 64];  // VoffO[i][j]
__device__ int   g_ei64;
__device__ int   g_ti64;

__device__ float g_X[(size_t)NN * 64];
__device__ float g_H0[(size_t)NN * 64];
__device__ float g_H1[(size_t)NN * 64];

// CSR structures (built once per call, reused for both layers)
__device__ int g_deg[NB * 256];
__device__ int g_start[NB * 256];
__device__ int g_cursor[NB * 256];
__device__ int g_bsum[1024];
__device__ int g_csr[MAXE];

// ---------------------------------------------------------------------------
// Kernel 1: precompute (blocks 0-3) + deg zeroing (blocks 4..NB+3)
// ---------------------------------------------------------------------------
__global__ void __launch_bounds__(256) precompute_kernel(
    const float* __restrict__ te,
    const float* __restrict__ Wq, const float* __restrict__ bq,
    const float* __restrict__ Wk, const float* __restrict__ bk,
    const float* __restrict__ Wv, const float* __restrict__ bv,
    const float* __restrict__ Wo,
    const void* __restrict__ ei_raw, const void* __restrict__ ti_raw)
{
    int t = threadIdx.x;
    int blk = blockIdx.x;

    if (blk >= 4) {                 // deg zeroing
        g_deg[(blk - 4) * 256 + t] = 0;
        return;
    }

    __shared__ float qoff[512], koff[512], voff[512];
    __shared__ float sWo[4096];

    for (int idx = t; idx < 512; idx += 256) {
        int tt = idx >> 6, d = idx & 63;
        float q = bq[d], k = bk[d], v = bv[d];
        for (int j = 0; j < 64; j++) {
            float x = __ldg(te + tt * 64 + j);
            q += x * __ldg(Wq + j * 64 + d);
            k += x * __ldg(Wk + j * 64 + d);
            v += x * __ldg(Wv + j * 64 + d);
        }
        qoff[idx] = q; koff[idx] = k; voff[idx] = v;
    }
    if (blk >= 1) {
        for (int i = t; i < 4096; i += 256) sWo[i] = __ldg(Wo + i);
    }
    __syncthreads();

    if (blk == 0) {
        for (int idx = t; idx < 2048; idx += 256) {
            int i = idx >> 6, j = idx & 63;
            int h = i >> 3, tt = i & 7;
            float s = 0.f;
            #pragma unroll
            for (int m = 0; m < 16; m++)
                s += __ldg(Wq + j * 64 + h * 16 + m) * koff[tt * 64 + h * 16 + m];
            g_P[idx] = 0.25f * s;
        }
        for (int idx = t; idx < 256; idx += 256) {
            int t0 = idx >> 5, i = idx & 31;
            int h = i >> 3, tt = i & 7;
            float s = 0.f;
            #pragma unroll
            for (int m = 0; m < 16; m++)
                s += qoff[t0 * 64 + h * 16 + m] * koff[tt * 64 + h * 16 + m];
            g_C[idx] = 0.25f * s;
        }
        if (t == 0) {
            const int* e32 = (const int*)ei_raw;
            const int* t32 = (const int*)ti_raw;
            int is64 = 1;
            for (int i = 0; i < 64; i++) if (e32[2 * i + 1] != 0) { is64 = 0; break; }
            g_ei64 = is64;
            is64 = 1;
            for (int i = 0; i < 64; i++) if (t32[2 * i + 1] != 0) { is64 = 0; break; }
            g_ti64 = is64;
        }
    } else if (blk == 1) {
        for (int idx = t; idx < 2048; idx += 256) {
            int i = idx >> 6, j = idx & 63;
            int h = i >> 3, tt = i & 7;
            float s = 0.f;
            #pragma unroll
            for (int m = 0; m < 16; m++)
                s += voff[tt * 64 + h * 16 + m] * sWo[(h * 16 + m) * 64 + j];
            g_VoffO[idx] = s;
        }
    } else {
        int kbase = (blk - 2) * 32;
        int k = kbase + (t >> 3);
        int j0 = (t & 7) * 8;
        float xv[64];
        #pragma unroll 16
        for (int d = 0; d < 64; d++) xv[d] = __ldg(Wv + k * 64 + d);
        float acc[8];
        #pragma unroll
        for (int j = 0; j < 8; j++) acc[j] = 0.f;
        for (int d = 0; d < 64; d++) {
            float x = xv[d];
            #pragma unroll
            for (int j = 0; j < 8; j++) acc[j] += x * sWo[d * 64 + j0 + j];
        }
        #pragma unroll
        for (int j = 0; j < 8; j++) g_WvWo[k * 64 + j0 + j] = acc[j];
    }
}

// ---------------------------------------------------------------------------
// CSR build kernels (unchanged, proven)
// ---------------------------------------------------------------------------
__global__ void __launch_bounds__(256) k_count(const void* __restrict__ ei_raw, int E)
{
    int e = blockIdx.x * 256 + threadIdx.x;
    if (e >= E) return;
    int dst;
    if (g_ei64) dst = (int)((const long long*)ei_raw)[(size_t)E + e];
    else        dst = ((const int*)ei_raw)[(size_t)E + e];
    atomicAdd(&g_deg[dst], 1);
}

__global__ void __launch_bounds__(256) k_bsum()
{
    __shared__ int sd[256];
    int t = threadIdx.x;
    sd[t] = g_deg[blockIdx.x * 256 + t];
    __syncthreads();
    for (int off = 128; off > 0; off >>= 1) {
        if (t < off) sd[t] += sd[t + off];
        __syncthreads();
    }
    if (t == 0) g_bsum[blockIdx.x] = sd[0];
}

__global__ void __launch_bounds__(1024) k_scan()
{
    __shared__ int sd[1024];
    int t = threadIdx.x;
    int v = (t < NB) ? g_bsum[t] : 0;
    sd[t] = v;
    __syncthreads();
    for (int off = 1; off < 1024; off <<= 1) {
        int u = (t >= off) ? sd[t - off] : 0;
        __syncthreads();
        sd[t] += u;
        __syncthreads();
    }
    if (t < NB) g_bsum[t] = sd[t] - v;   // exclusive
}

__global__ void __launch_bounds__(256) k_offsets()
{
    __shared__ int sd[256];
    int t = threadIdx.x;
    int n = blockIdx.x * 256 + t;
    int v = g_deg[n];
    sd[t] = v;
    __syncthreads();
    for (int off = 1; off < 256; off <<= 1) {
        int u = (t >= off) ? sd[t - off] : 0;
        __syncthreads();
        sd[t] += u;
        __syncthreads();
    }
    int start = g_bsum[blockIdx.x] + sd[t] - v;
    g_start[n] = start;
    g_cursor[n] = start;
}

__global__ void __launch_bounds__(256) k_fill(const void* __restrict__ ei_raw, int E)
{
    int e = blockIdx.x * 256 + threadIdx.x;
    if (e >= E) return;
    int src, dst;
    if (g_ei64) {
        const long long* p = (const long long*)ei_raw;
        src = (int)p[e];
        dst = (int)p[(size_t)E + e];
    } else {
        const int* p = (const int*)ei_raw;
        src = p[e];
        dst = p[(size_t)E + e];
    }
    int slot = atomicAdd(&g_cursor[dst], 1);
    g_csr[slot] = src;
}

// ---------------------------------------------------------------------------
// node kernel — R3 proven form (warp per 4 nodes, persistent grid).
// ---------------------------------------------------------------------------
__device__ __forceinline__ float softmax8(float s)
{
    const unsigned FULL = 0xffffffffu;
    float m = fmaxf(s, __shfl_xor_sync(FULL, s, 1));
    m = fmaxf(m, __shfl_xor_sync(FULL, m, 2));
    m = fmaxf(m, __shfl_xor_sync(FULL, m, 4));
    float e = __expf(s - m);
    float t = e + __shfl_xor_sync(FULL, e, 1);
    t += __shfl_xor_sync(FULL, t, 2);
    t += __shfl_xor_sync(FULL, t, 4);
    return e / t;
}

__global__ void __launch_bounds__(256) node_kernel(
    const float* __restrict__ user_emb,
    const float* __restrict__ item_emb,
    const void* __restrict__ ti_raw,
    const float* __restrict__ te,
    const float* __restrict__ bo,
    const float* __restrict__ causal,
    int numTiles)
{
    __shared__ float sP[32 * 65];
    __shared__ float sW[64 * 64];
    __shared__ float sVO[32 * 64];
    __shared__ float sC[256];
    __shared__ float sTE[8 * 64];
    __shared__ float sBO[64];
    __shared__ float sX[8][4][64];

    int tid = threadIdx.x;
    for (int idx = tid; idx < 32 * 64; idx += 256) {
        sP[(idx >> 6) * 65 + (idx & 63)] = g_P[idx];
        sVO[idx] = g_VoffO[idx];
    }
    for (int idx = tid; idx < 64 * 64; idx += 256) sW[idx] = g_WvWo[idx];
    if (tid < 256) sC[tid] = g_C[tid];
    for (int idx = tid; idx < 512; idx += 256) sTE[idx] = te[idx];
    if (tid < 64) sBO[tid] = bo[tid];
    int ti64 = g_ti64;
    __syncthreads();

    int w = tid >> 5, lane = tid & 31;
    const long long* tp64 = (const long long*)ti_raw;
    const int*       tp32 = (const int*)ti_raw;
    const unsigned FULL = 0xffffffffu;

    float* x0 = &sX[w][0][0];
    float* x1 = &sX[w][1][0];
    float* x2 = &sX[w][2][0];
    float* x3 = &sX[w][3][0];

    for (int tile = blockIdx.x; tile < numTiles; tile += gridDim.x) {
        int base = tile * 32 + w * 4;
        int t0a = 0, t0b = 0, t0c = 0, t0d = 0;

        #pragma unroll
        for (int m = 0; m < 4; m++) {
            int n = base + m;
            float2 xv = make_float2(0.f, 0.f);
            int tt = 0;
            if (n < NN) {
                const float* src = (n < NU) ? (user_emb + (size_t)n * 64)
                                            : (item_emb + (size_t)(n - NU) * 64);
                xv = ((const float2*)src)[lane];
                tt = ti64 ? (int)tp64[n] : tp32[n];
            }
            sX[w][m][2 * lane]     = xv.x;
            sX[w][m][2 * lane + 1] = xv.y;
            if (m == 0) t0a = tt; else if (m == 1) t0b = tt;
            else if (m == 2) t0c = tt; else t0d = tt;
        }
        __syncwarp();

        float s0 = 0.f, s1 = 0.f, s2 = 0.f, s3 = 0.f;
        const float* pr = sP + lane * 65;
        #pragma unroll 8
        for (int j = 0; j < 64; j++) {
            float p = pr[j];
            s0 += p * x0[j]; s1 += p * x1[j];
            s2 += p * x2[j]; s3 += p * x3[j];
        }
        s0 += sC[t0a * 32 + lane];
        s1 += sC[t0b * 32 + lane];
        s2 += sC[t0c * 32 + lane];
        s3 += sC[t0d * 32 + lane];

        float a0 = softmax8(s0);
        float a1 = softmax8(s1);
        float a2 = softmax8(s2);
        float a3 = softmax8(s3);

        float bx = sBO[2 * lane], by = sBO[2 * lane + 1];
        float2 acc0, acc1, acc2, acc3;
        acc0.x = bx + sTE[t0a * 64 + 2 * lane]     + x0[2 * lane];
        acc0.y = by + sTE[t0a * 64 + 2 * lane + 1] + x0[2 * lane + 1];
        acc1.x = bx + sTE[t0b * 64 + 2 * lane]     + x1[2 * lane];
        acc1.y = by + sTE[t0b * 64 + 2 * lane + 1] + x1[2 * lane + 1];
        acc2.x = bx + sTE[t0c * 64 + 2 * lane]     + x2[2 * lane];
        acc2.y = by + sTE[t0c * 64 + 2 * lane + 1] + x2[2 * lane + 1];
        acc3.x = bx + sTE[t0d * 64 + 2 * lane]     + x3[2 * lane];
        acc3.y = by + sTE[t0d * 64 + 2 * lane + 1] + x3[2 * lane + 1];

        #pragma unroll 8
        for (int i = 0; i < 32; i++) {
            float2 v = *(const float2*)(sVO + i * 64 + 2 * lane);
            float b0 = __shfl_sync(FULL, a0, i);
            float b1 = __shfl_sync(FULL, a1, i);
            float b2 = __shfl_sync(FULL, a2, i);
            float b3 = __shfl_sync(FULL, a3, i);
            acc0.x += b0 * v.x; acc0.y += b0 * v.y;
            acc1.x += b1 * v.x; acc1.y += b1 * v.y;
            acc2.x += b2 * v.x; acc2.y += b2 * v.y;
            acc3.x += b3 * v.x; acc3.y += b3 * v.y;
        }

        #pragma unroll 8
        for (int k = 0; k < 64; k++) {
            float2 v = *(const float2*)(sW + k * 64 + 2 * lane);
            float h0 = x0[k], h1 = x1[k], h2 = x2[k], h3 = x3[k];
            acc0.x += h0 * v.x; acc0.y += h0 * v.y;
            acc1.x += h1 * v.x; acc1.y += h1 * v.y;
            acc2.x += h2 * v.x; acc2.y += h2 * v.y;
            acc3.x += h3 * v.x; acc3.y += h3 * v.y;
        }

        #pragma unroll
        for (int m = 0; m < 4; m++) {
            int n = base + m;
            if (n >= NN) continue;
            float2 r = (m == 0) ? acc0 : (m == 1) ? acc1 : (m == 2) ? acc2 : acc3;
            float2 c = ((const float2*)(causal + (size_t)n * 64))[lane];
            ((float2*)(g_X + (size_t)n * 64))[lane] = r;
            float2 h;
            h.x = r.x + 0.5f * c.x;
            h.y = r.y + 0.5f * c.y;
            ((float2*)(g_H0 + (size_t)n * 64))[lane] = h;
        }
        __syncwarp();
    }
}

// ---------------------------------------------------------------------------
// dense kernel v3 — warp per 4 nodes, fused CSR gather, packed weights.
// Per k per 4 nodes: 2x LDS.64 weights (4 wf) + 4x broadcast LDS.64 {h,a} (4 wf)
// + 8 FFMA2 into 8 independent chains (self/neigh split, summed at epilogue).
// Exactly 48KB static smem -> 4 blocks/SM.
// mode 0: relu(h0@Ws + agg@Wn + b) -> g_H1
// mode 1: out = g_X + relu(h1@Ws + agg@Wn + b)  (+ dup copy)
// ---------------------------------------------------------------------------
__global__ void __launch_bounds__(256) dense_kernel(
    const float* __restrict__ Ws, const float* __restrict__ Wn,
    const float* __restrict__ bb,
    float* __restrict__ out, int dup, int numGroups, int mode)
{
    __shared__ ull    sWs2[64][32];     // 16KB : pack(Ws[k][2l], Ws[k][2l+1])
    __shared__ ull    sWn2[64][32];     // 16KB : pack(Wn[k][2l], Wn[k][2l+1])
    __shared__ float2 sIn[8][4][64];    // 16KB : per warp/node, {h[k], a[k]}

    int t = threadIdx.x;
    int w = t >> 5, lane = t & 31;

    for (int i = t; i < 2048; i += 256) {
        int k = i >> 5, l = i & 31;
        float2 ws = __ldg((const float2*)(Ws + k * 64) + l);
        float2 wn = __ldg((const float2*)(Wn + k * 64) + l);
        sWs2[k][l] = pack2(ws.x, ws.y);
        sWn2[k][l] = pack2(wn.x, wn.y);
    }
    __syncthreads();

    float2 b2 = __ldg((const float2*)bb + lane);
    const float* __restrict__ Hin = mode ? g_H1 : g_H0;

    int gwarp = blockIdx.x * 8 + w;
    int nWarps = gridDim.x * 8;

    for (int gi = gwarp; gi < numGroups; gi += nWarps) {
        int base = gi * 4;

        // stage {h, a} interleaved; a = fused CSR gather over neighbors
        #pragma unroll
        for (int m = 0; m < 4; m++) {
            int n = base + m;
            float2 h = make_float2(0.f, 0.f);
            float2 a = make_float2(0.f, 0.f);
            if (n < NN) {
                h = __ldg((const float2*)(Hin + (size_t)n * 64) + lane);
                int s = g_start[n];
                int end = s + g_deg[n];
                int j = s;
                for (; j + 3 < end; j += 4) {
                    int i0 = __ldg(g_csr + j);
                    int i1 = __ldg(g_csr + j + 1);
                    int i2 = __ldg(g_csr + j + 2);
                    int i3 = __ldg(g_csr + j + 3);
                    float2 v0 = __ldg((const float2*)(Hin + (size_t)i0 * 64) + lane);
                    float2 v1 = __ldg((const float2*)(Hin + (size_t)i1 * 64) + lane);
                    float2 v2 = __ldg((const float2*)(Hin + (size_t)i2 * 64) + lane);
                    float2 v3 = __ldg((const float2*)(Hin + (size_t)i3 * 64) + lane);
                    a.x += v0.x + v1.x + v2.x + v3.x;
                    a.y += v0.y + v1.y + v2.y + v3.y;
                }
                for (; j < end; j++) {
                    int i0 = __ldg(g_csr + j);
                    float2 v0 = __ldg((const float2*)(Hin + (size_t)i0 * 64) + lane);
                    a.x += v0.x;
                    a.y += v0.y;
                }
            }
            // sIn[w][m][2l] = {h.x, a.x}; sIn[w][m][2l+1] = {h.y, a.y}
            float4 pk = make_float4(h.x, a.x, h.y, a.y);
            *(float4*)&sIn[w][m][2 * lane] = pk;
        }
        __syncwarp();

        ull accS0 = 0, accS1 = 0, accS2 = 0, accS3 = 0;
        ull accN0 = 0, accN1 = 0, accN2 = 0, accN3 = 0;
        #pragma unroll 8
        for (int k = 0; k < 64; k++) {
            ull ws = sWs2[k][lane];
            ull wn = sWn2[k][lane];
            float2 ha0 = sIn[w][0][k];
            float2 ha1 = sIn[w][1][k];
            float2 ha2 = sIn[w][2][k];
            float2 ha3 = sIn[w][3][k];
            fma2(accS0, pack2(ha0.x, ha0.x), ws);
            fma2(accN0, pack2(ha0.y, ha0.y), wn);
            fma2(accS1, pack2(ha1.x, ha1.x), ws);
            fma2(accN1, pack2(ha1.y, ha1.y), wn);
            fma2(accS2, pack2(ha2.x, ha2.x), ws);
            fma2(accN2, pack2(ha2.y, ha2.y), wn);
            fma2(accS3, pack2(ha3.x, ha3.x), ws);
            fma2(accN3, pack2(ha3.y, ha3.y), wn);
        }

        #pragma unroll
        for (int m = 0; m < 4; m++) {
            int n = base + m;
            if (n >= NN) continue;
            ull as = (m == 0) ? accS0 : (m == 1) ? accS1 : (m == 2) ? accS2 : accS3;
            ull an = (m == 0) ? accN0 : (m == 1) ? accN1 : (m == 2) ? accN2 : accN3;
            float2 rs = unpack2(as);
            float2 rn = unpack2(an);
            float rx = fmaxf(rs.x + rn.x + b2.x, 0.f);
            float ry = fmaxf(rs.y + rn.y + b2.y, 0.f);
            if (mode == 0) {
                *((float2*)(g_H1 + (size_t)n * 64) + lane) = make_float2(rx, ry);
            } else {
                float2 xv = __ldg((const float2*)(g_X + (size_t)n * 64) + lane);
                float2 r = make_float2(xv.x + rx, xv.y + ry);
                *((float2*)(out + (size_t)n * 64) + lane) = r;
                if (dup)
                    *((float2*)(out + (size_t)(NN + n) * 64) + lane) = r;
            }
        }
        __syncwarp();
    }
}

// ---------------------------------------------------------------------------
// kernel_launch
// ---------------------------------------------------------------------------
extern "C" void kernel_launch(void* const* d_in, const int* in_sizes, int n_in,
                              void* d_out, int out_size)
{
    const void*  ei     = d_in[0];
    const void*  ti     = d_in[2];
    const float* user   = (const float*)d_in[3];
    const float* item   = (const float*)d_in[4];
    const float* te     = (const float*)d_in[5];
    const float* causal = (const float*)d_in[6];
    const float* Wq = (const float*)d_in[7],  *bq = (const float*)d_in[8];
    const float* Wk = (const float*)d_in[9],  *bk = (const float*)d_in[10];
    const float* Wv = (const float*)d_in[11], *bv = (const float*)d_in[12];
    const float* Wo = (const float*)d_in[13], *bo = (const float*)d_in[14];
    const float* Ws0 = (const float*)d_in[15], *Wn0 = (const float*)d_in[16];
    const float* b0  = (const float*)d_in[17];
    const float* Ws1 = (const float*)d_in[18], *Wn1 = (const float*)d_in[19];
    const float* b1  = (const float*)d_in[20];

    int E = in_sizes[1];
    if (E > MAXE) E = MAXE;
    float* out = (float*)d_out;
    int dup = (out_size >= 2 * NN * 64) ? 1 : 0;

    int nodeTiles  = (NN + 31) / 32;      // 4688
    int denseGroups = (NN + 3) / 4;       // 37500
    int edgeBlocks = (E + 255) / 256;     // 9375

    // precompute (blocks 0-3) + deg zeroing (blocks 4..NB+3)
    precompute_kernel<<<NB + 4, 256>>>(te, Wq, bq, Wk, bk, Wv, bv, Wo, ei, ti);

    // CSR build
    k_count<<<edgeBlocks, 256>>>(ei, E);
    k_bsum<<<NB, 256>>>();
    k_scan<<<1, 1024>>>();
    k_offsets<<<NB, 256>>>();
    k_fill<<<edgeBlocks, 256>>>(ei, E);

    node_kernel<<<1184, 256>>>(user, item, ti, te, bo, causal, nodeTiles);
    dense_kernel<<<1184, 256>>>(Ws0, Wn0, b0, nullptr, 0, denseGroups, 0);
    dense_kernel<<<1184, 256>>>(Ws1, Wn1, b1, out, dup, denseGroups, 1);
}